// round 16
// baseline (speedup 1.0000x reference)
#include <cuda_runtime.h>
#include <stdint.h>

#define HW   3136
#define WD   56
#define NB   32
#define CIN  240
#define MID  120
#define COUT 480

// Scratch (allocation-free rule: __device__ globals)
__device__ float g_y1[(size_t)NB * MID * HW];   // conv1 output (post BN+ReLU)
__device__ float g_y2[(size_t)NB * MID * HW];   // depthwise output, SHUFFLED channel order

// Pre-duplicated weight layouts (filled by prep_kernel each call):
//  g_w1d  [g][k=80][80]   : 40 oc duplicated pairwise
//  g_w3d  [g][k=40][320]  : 160 oc duplicated pairwise
//  g_wscd [k=240][960]    : 480 oc duplicated pairwise
__device__ float g_w1d[3 * 80 * 80];
__device__ float g_w3d[3 * 40 * 320];
__device__ float g_wscd[240 * 960];

typedef unsigned long long u64;

__device__ __forceinline__ u64 fma2(u64 a, u64 b, u64 c) {
    u64 d; asm("fma.rn.f32x2 %0, %1, %2, %3;" : "=l"(d) : "l"(a), "l"(b), "l"(c)); return d;
}
__device__ __forceinline__ float2 unpack2(u64 v) {
    float2 r; asm("mov.b64 {%0, %1}, %2;" : "=f"(r.x), "=f"(r.y) : "l"(v)); return r;
}
__device__ __forceinline__ u64 pack2(float a, float b) {
    u64 r; asm("mov.b64 %0, {%1, %2};" : "=l"(r) : "f"(a), "f"(b)); return r;
}
__device__ __forceinline__ uint32_t saddr(const void* p) {
    return (uint32_t)__cvta_generic_to_shared(p);
}
__device__ __forceinline__ void cp16(uint32_t dst, const void* src) {
    asm volatile("cp.async.cg.shared.global [%0], [%1], 16;\n"
                 :: "r"(dst), "l"(src));
}
#define CP_COMMIT() asm volatile("cp.async.commit_group;\n" ::: "memory")
#define CP_WAIT1()  asm volatile("cp.async.wait_group 1;\n" ::: "memory")
#define CP_WAIT0()  asm volatile("cp.async.wait_group 0;\n" ::: "memory")

// ---------------------------------------------------------------------------
// prep: duplicate weights pairwise into [k][2*oc] layouts (tiny)
// ---------------------------------------------------------------------------
__global__ __launch_bounds__(256) void prep_kernel(
    const float* __restrict__ w1, const float* __restrict__ w3,
    const float* __restrict__ wsc)
{
    const int tid = blockIdx.x * 256 + threadIdx.x;
    if (tid < 9600) {                     // w1: 3 groups x 40 oc x 80 k
        int g = tid / 3200, r = tid % 3200;
        int oc = r / 80, k = r % 80;
        float v = w1[(g * 40 + oc) * 80 + k];
        float* d = g_w1d + ((size_t)(g * 80 + k)) * 80 + 2 * oc;
        d[0] = v; d[1] = v;
    }
    if (tid < 19200) {                    // w3: 3 groups x 160 oc x 40 k
        int g = tid / 6400, r = tid % 6400;
        int oc = r / 40, k = r % 40;
        float v = w3[(g * 160 + oc) * 40 + k];
        float* d = g_w3d + ((size_t)(g * 40 + k)) * 320 + 2 * oc;
        d[0] = v; d[1] = v;
    }
    if (tid < 115200) {                   // wsc: 480 oc x 240 k
        int oc = tid / 240, k = tid % 240;
        float v = wsc[oc * 240 + k];
        float* d = g_wscd + (size_t)k * 960 + 2 * oc;
        d[0] = v; d[1] = v;
    }
}

// ---------------------------------------------------------------------------
// K1: grouped 1x1 conv (40oc x 80ic per group) + BN + ReLU -> g_y1
// grid (49, 3, 32), block 160.  K-tile = 8 (10 tiles), 3-stage cp.async.
// Inner loop: 8 FFMA2 + 3 LDS.128, zero MOVs.  smem 13.8KB -> high occupancy.
// ---------------------------------------------------------------------------
__global__ __launch_bounds__(160, 8) void conv1_kernel(
    const float* __restrict__ x,
    const float* __restrict__ scale1, const float* __restrict__ shift1)
{
    __shared__ __align__(16) float sX[3][8][64];
    __shared__ __align__(16) float sW[3][8][80];
    const int tid = threadIdx.x;
    const int tx = tid & 15, ty = tid >> 4;          // tx: 4hw, ty: 4oc (0..9)
    const int n = blockIdx.z, g = blockIdx.y;
    const int hw0 = blockIdx.x * 64;
    const float* xg = x + ((size_t)n * CIN + g * 80) * HW + hw0;
    const float* wg = g_w1d + (size_t)g * 80 * 80;

    // X: 128 chunks of 16B; W: 160 chunks (1/thread)
    const bool hx = tid < 128;
    const int kx = tid >> 4, jx = (tid & 15) * 4;
    const int kw = tid / 20, ow = (tid % 20) * 4;

    u64 acc[4][2];
    #pragma unroll
    for (int i = 0; i < 4; i++) { acc[i][0] = 0ull; acc[i][1] = 0ull; }

    auto issue = [&](int t) {
        const int b = t % 3, kk = t * 8;
        if (hx) cp16(saddr(&sX[b][kx][jx]), xg + (size_t)(kk + kx) * HW + jx);
        cp16(saddr(&sW[b][kw][ow]), wg + (size_t)(kk + kw) * 80 + ow);
        CP_COMMIT();
    };

    issue(0); issue(1);
    for (int t = 0; t < 10; t++) {
        if (t < 9) CP_WAIT1(); else CP_WAIT0();
        __syncthreads();
        if (t + 2 < 10) issue(t + 2);
        const int b = t % 3;
        #pragma unroll
        for (int k = 0; k < 8; k++) {
            const ulonglong2 w01 = *(const ulonglong2*)&sW[b][k][ty * 8];
            const ulonglong2 w23 = *(const ulonglong2*)&sW[b][k][ty * 8 + 4];
            const ulonglong2 xp  = *(const ulonglong2*)&sX[b][k][tx * 4];
            acc[0][0] = fma2(w01.x, xp.x, acc[0][0]); acc[0][1] = fma2(w01.x, xp.y, acc[0][1]);
            acc[1][0] = fma2(w01.y, xp.x, acc[1][0]); acc[1][1] = fma2(w01.y, xp.y, acc[1][1]);
            acc[2][0] = fma2(w23.x, xp.x, acc[2][0]); acc[2][1] = fma2(w23.x, xp.y, acc[2][1]);
            acc[3][0] = fma2(w23.y, xp.x, acc[3][0]); acc[3][1] = fma2(w23.y, xp.y, acc[3][1]);
        }
    }

    float* yb = g_y1 + (size_t)n * MID * HW;
    #pragma unroll
    for (int i = 0; i < 4; i++) {
        int oc = g * 40 + ty * 4 + i;
        float sc = scale1[oc], sh = shift1[oc];
        float2 v0 = unpack2(acc[i][0]), v1 = unpack2(acc[i][1]);
        float4 o;
        o.x = fmaxf(fmaf(v0.x, sc, sh), 0.f);
        o.y = fmaxf(fmaf(v0.y, sc, sh), 0.f);
        o.z = fmaxf(fmaf(v1.x, sc, sh), 0.f);
        o.w = fmaxf(fmaf(v1.y, sc, sh), 0.f);
        *(float4*)&yb[(size_t)oc * HW + hw0 + tx * 4] = o;
    }
}

// ---------------------------------------------------------------------------
// K2: depthwise 3x3 (pad 1) + BN2, write in SHUFFLED channel order.
// source c writes to dst = (c%40)*3 + c/40
// ---------------------------------------------------------------------------
__global__ __launch_bounds__(256) void dw_kernel(
    const float* __restrict__ w2, const float* __restrict__ scale2,
    const float* __restrict__ shift2)
{
    const int n = blockIdx.z, c = blockIdx.y;
    const int p = blockIdx.x * 256 + threadIdx.x;
    if (p >= HW) return;
    const int h = p / WD, w = p % WD;
    const float* src = g_y1 + ((size_t)n * MID + c) * HW;
    const float* wr = w2 + c * 9;
    float s = 0.f;
    #pragma unroll
    for (int kh = 0; kh < 3; kh++) {
        int hh = h + kh - 1;
        if (hh < 0 || hh >= WD) continue;
        const float* row = src + hh * WD;
        #pragma unroll
        for (int kw = 0; kw < 3; kw++) {
            int ww = w + kw - 1;
            if (ww >= 0 && ww < WD) s = fmaf(row[ww], wr[kh * 3 + kw], s);
        }
    }
    float v = fmaf(s, scale2[c], shift2[c]);
    const int dst = (c % 40) * 3 + c / 40;
    g_y2[((size_t)n * MID + dst) * HW + p] = v;
}

// ---------------------------------------------------------------------------
// K3: grouped 1x1 conv3 (40 shuffled ic) + BN3 + ReLU, plus full 1x1 shortcut
// (240 ic) + BN_sc, fused add -> out.
// grid (49, 6, 32), block 160.  Tile 80oc x 64hw; per-thread 8oc x 4hw.
// K-tile = 8: 5 conv3 tiles (K=40 exact) + 30 shortcut tiles = 35 total.
// After tile 4 the conv3 result is folded into the accumulator as
// (relu(bn3)+sb)/ss, so final = ss*acc — no yr registers, regs ~50.
// smem 21KB, 3-stage pipeline, issue-before-compute, 1 sync/tile.
// ---------------------------------------------------------------------------
__global__ __launch_bounds__(160, 7) void conv3_kernel(
    const float* __restrict__ x,
    const float* __restrict__ scale3, const float* __restrict__ shift3,
    const float* __restrict__ scale_sc, const float* __restrict__ shift_sc,
    float* __restrict__ out)
{
    __shared__ __align__(16) float sX[3][8][64];
    __shared__ __align__(16) float sW[3][8][160];
    const int tid = threadIdx.x;
    const int tx = tid & 15, ty = tid >> 4;          // tx: 4hw, ty: 8oc (0..9)
    const int n = blockIdx.z;
    const int yq = blockIdx.y;                        // 0..5 -> 80-oc tile
    const int gsel = yq >> 1, half = yq & 1;
    const int oc_base = yq * 80;
    const int hw0 = blockIdx.x * 64;

    const float* y2g  = g_y2 + ((size_t)n * MID + gsel * 40) * HW + hw0;
    const float* xn   = x + (size_t)n * CIN * HW + hw0;
    const float* w3g  = g_w3d + (size_t)(gsel * 40) * 320 + half * 160;
    const float* wscg = g_wscd + (size_t)yq * 160;

    // X: 128 chunks of 16B; W: 320 chunks (2/thread)
    const bool hx = tid < 128;
    const int kx = tid >> 4, jx = (tid & 15) * 4;
    const int kwa = tid / 40, owa = (tid % 40) * 4;          // chunk tid
    const int kwb = (tid + 160) / 40, owb = ((tid + 160) % 40) * 4;  // chunk tid+160

    u64 acc[8][2];
    #pragma unroll
    for (int i = 0; i < 8; i++) { acc[i][0] = 0ull; acc[i][1] = 0ull; }

    auto issue = [&](int t) {
        const int b = t % 3;
        if (t < 5) {                                  // conv3: K 0..39
            const int kk = t * 8;
            if (hx) cp16(saddr(&sX[b][kx][jx]), y2g + (size_t)(kk + kx) * HW + jx);
            cp16(saddr(&sW[b][kwa][owa]), w3g + (size_t)(kk + kwa) * 320 + owa);
            cp16(saddr(&sW[b][kwb][owb]), w3g + (size_t)(kk + kwb) * 320 + owb);
        } else {                                      // shortcut: K 0..239
            const int kk = (t - 5) * 8;
            if (hx) cp16(saddr(&sX[b][kx][jx]), xn + (size_t)(kk + kx) * HW + jx);
            cp16(saddr(&sW[b][kwa][owa]), wscg + (size_t)(kk + kwa) * 960 + owa);
            cp16(saddr(&sW[b][kwb][owb]), wscg + (size_t)(kk + kwb) * 960 + owb);
        }
        CP_COMMIT();
    };

    issue(0); issue(1);
    for (int t = 0; t < 35; t++) {
        if (t < 34) CP_WAIT1(); else CP_WAIT0();
        __syncthreads();
        if (t + 2 < 35) issue(t + 2);
        const int b = t % 3;
        #pragma unroll
        for (int k = 0; k < 8; k++) {
            const ulonglong2 w01 = *(const ulonglong2*)&sW[b][k][ty * 16];
            const ulonglong2 w23 = *(const ulonglong2*)&sW[b][k][ty * 16 + 4];
            const ulonglong2 w45 = *(const ulonglong2*)&sW[b][k][ty * 16 + 8];
            const ulonglong2 w67 = *(const ulonglong2*)&sW[b][k][ty * 16 + 12];
            const ulonglong2 xp  = *(const ulonglong2*)&sX[b][k][tx * 4];
            acc[0][0] = fma2(w01.x, xp.x, acc[0][0]); acc[0][1] = fma2(w01.x, xp.y, acc[0][1]);
            acc[1][0] = fma2(w01.y, xp.x, acc[1][0]); acc[1][1] = fma2(w01.y, xp.y, acc[1][1]);
            acc[2][0] = fma2(w23.x, xp.x, acc[2][0]); acc[2][1] = fma2(w23.x, xp.y, acc[2][1]);
            acc[3][0] = fma2(w23.y, xp.x, acc[3][0]); acc[3][1] = fma2(w23.y, xp.y, acc[3][1]);
            acc[4][0] = fma2(w45.x, xp.x, acc[4][0]); acc[4][1] = fma2(w45.x, xp.y, acc[4][1]);
            acc[5][0] = fma2(w45.y, xp.x, acc[5][0]); acc[5][1] = fma2(w45.y, xp.y, acc[5][1]);
            acc[6][0] = fma2(w67.x, xp.x, acc[6][0]); acc[6][1] = fma2(w67.x, xp.y, acc[6][1]);
            acc[7][0] = fma2(w67.y, xp.x, acc[7][0]); acc[7][1] = fma2(w67.y, xp.y, acc[7][1]);
        }
        if (t == 4) {
            // conv3 done: acc <- (relu(bn3(acc)) + sb) / ss, so final = ss*acc
            #pragma unroll
            for (int i = 0; i < 8; i++) {
                int oc = oc_base + ty * 8 + i;
                float s3 = scale3[oc], b3 = shift3[oc];
                float inv = 1.0f / scale_sc[oc];
                float sb = shift_sc[oc];
                #pragma unroll
                for (int p = 0; p < 2; p++) {
                    float2 v = unpack2(acc[i][p]);
                    float r0 = fmaxf(fmaf(v.x, s3, b3), 0.f) + sb;
                    float r1 = fmaxf(fmaf(v.y, s3, b3), 0.f) + sb;
                    acc[i][p] = pack2(r0 * inv, r1 * inv);
                }
            }
        }
    }

    // final: out = ss * acc
    float* ob = out + (size_t)n * COUT * HW;
    #pragma unroll
    for (int i = 0; i < 8; i++) {
        int oc = oc_base + ty * 8 + i;
        float ss = scale_sc[oc];
        float2 z0 = unpack2(acc[i][0]), z1 = unpack2(acc[i][1]);
        float4 o;
        o.x = z0.x * ss;
        o.y = z0.y * ss;
        o.z = z1.x * ss;
        o.w = z1.y * ss;
        *(float4*)&ob[(size_t)oc * HW + hw0 + tx * 4] = o;
    }
}

// ---------------------------------------------------------------------------
extern "C" void kernel_launch(void* const* d_in, const int* in_sizes, int n_in,
                              void* d_out, int out_size)
{
    const float* x        = (const float*)d_in[0];
    const float* w1       = (const float*)d_in[1];
    const float* scale1   = (const float*)d_in[2];
    const float* shift1   = (const float*)d_in[3];
    const float* w2       = (const float*)d_in[4];
    const float* scale2   = (const float*)d_in[5];
    const float* shift2   = (const float*)d_in[6];
    const float* w3       = (const float*)d_in[7];
    const float* scale3   = (const float*)d_in[8];
    const float* shift3   = (const float*)d_in[9];
    const float* wsc      = (const float*)d_in[10];
    const float* scale_sc = (const float*)d_in[11];
    const float* shift_sc = (const float*)d_in[12];
    // d_in[13] = groups (always 3), baked in at compile time
    float* out = (float*)d_out;

    prep_kernel<<<450, 256>>>(w1, w3, wsc);
    conv1_kernel<<<dim3(49, 3, NB), 160>>>(x, scale1, shift1);
    dw_kernel<<<dim3((HW + 255) / 256, MID, NB), 256>>>(w2, scale2, shift2);
    conv3_kernel<<<dim3(49, 6, NB), 160>>>(x, scale3, shift3,
                                           scale_sc, shift_sc, out);
}